// round 6
// baseline (speedup 1.0000x reference)
#include <cuda_runtime.h>

// ============================================================================
// CausalScaledDotAttention  (B=4, S=2048, H=1024, fp32)
//   q = Xq @ Wq^T + bq ; k = ... ; v = ...
//   scores[b,s,t] = <k_s, q_t> / sqrt(H), causal mask s>t -> -1e7
//   attn = softmax over s ;  context[b,t,h] = sum_s attn[b,s,t] v[b,s,h]
//   output = concat(context.flatten(), attn.flatten())
// ============================================================================

#define BATCH  4
#define SEQ    2048
#define HID    1024
#define BSROWS (BATCH * SEQ)
#define SCALE  0.03125f   // 1/sqrt(1024)

// Scratch (static device memory; allocation-free per harness rules)
__device__ float g_q[(size_t)BSROWS * HID];
__device__ float g_k[(size_t)BSROWS * HID];
__device__ float g_v[(size_t)BSROWS * HID];
// scores/probs, t-major per batch: g_p[b][t][s]
__device__ float g_p[(size_t)BATCH * SEQ * SEQ];

typedef unsigned long long ull;

union U64 { ull u; float2 f; };

__device__ __forceinline__ ull dup2(float x) {
    ull r;
    asm("mov.b64 %0, {%1, %1};" : "=l"(r) : "f"(x));
    return r;
}

// packed fp32x2 FMA (sm_100+): d = a*b + d, elementwise on the two lanes
__device__ __forceinline__ void fma2(ull& d, ull a, ull b) {
    asm("fma.rn.f32x2 %0, %1, %2, %3;" : "=l"(d) : "l"(a), "l"(b), "l"(d));
}

// ----------------------------------------------------------------------------
// 128x128 tile GEMM core, BK=8, 256 threads, 8x8 microtile per thread.
//   C[i,j] = sum_k A[i,k] * B'[.,.]
//   B_KMAJOR = true : B'[j,k] = Bm[j*ldb + k]   (NT: proj, scores)
//   B_KMAJOR = false: B'[j,k] = Bm[k*ldb + j]   (NN: context)
// A is staged in smem duplicated into 64-bit lanes so the inner loop is pure
// LDS.128 + fma.rn.f32x2. Accumulators are fp32 pairs over adjacent j.
// ----------------------------------------------------------------------------
template <bool B_KMAJOR>
__device__ __forceinline__ void gemm128(const float* __restrict__ A, int lda,
                                        const float* __restrict__ Bm, int ldb,
                                        int i0, int j0, int kTotal,
                                        ull acc[8][4]) {
    __shared__ ull   As[8][128];   // duplicated A values
    __shared__ float Bs[8][128];

    const int tid = threadIdx.x;
    const int tx  = tid & 15;      // j-tile of 8 cols (4 pairs)
    const int ty  = tid >> 4;      // i-tile of 8 rows
    const int lr  = tid >> 1;      // loader row 0..127
    const int lk  = (tid & 1) * 4; // loader k offset 0/4
    const int br  = tid >> 5;      // NN loader: k row 0..7
    const int bc  = (tid & 31) * 4;// NN loader: col 0..124

    float4 aReg = *(const float4*)(A + (size_t)(i0 + lr) * lda + lk);
    float4 bReg = B_KMAJOR
        ? *(const float4*)(Bm + (size_t)(j0 + lr) * ldb + lk)
        : *(const float4*)(Bm + (size_t)br * ldb + j0 + bc);

    int k0 = 0;
    while (true) {
        As[lk + 0][lr] = dup2(aReg.x);
        As[lk + 1][lr] = dup2(aReg.y);
        As[lk + 2][lr] = dup2(aReg.z);
        As[lk + 3][lr] = dup2(aReg.w);
        if (B_KMAJOR) {
            Bs[lk + 0][lr] = bReg.x;
            Bs[lk + 1][lr] = bReg.y;
            Bs[lk + 2][lr] = bReg.z;
            Bs[lk + 3][lr] = bReg.w;
        } else {
            *(float4*)&Bs[br][bc] = bReg;
        }
        __syncthreads();

        const int kn = k0 + 8;
        if (kn < kTotal) {  // prefetch next tile into registers
            aReg = *(const float4*)(A + (size_t)(i0 + lr) * lda + kn + lk);
            bReg = B_KMAJOR
                ? *(const float4*)(Bm + (size_t)(j0 + lr) * ldb + kn + lk)
                : *(const float4*)(Bm + (size_t)(kn + br) * ldb + j0 + bc);
        }

#pragma unroll
        for (int k = 0; k < 8; k++) {
            const ulonglong2* ap = (const ulonglong2*)&As[k][ty * 8];
            ulonglong2 aa0 = ap[0], aa1 = ap[1], aa2 = ap[2], aa3 = ap[3];
            const ulonglong2* bp = (const ulonglong2*)&Bs[k][tx * 8];
            ulonglong2 bb0 = bp[0], bb1 = bp[1];
            ull a2[8] = {aa0.x, aa0.y, aa1.x, aa1.y, aa2.x, aa2.y, aa3.x, aa3.y};
            ull b2[4] = {bb0.x, bb0.y, bb1.x, bb1.y};
#pragma unroll
            for (int m = 0; m < 8; m++)
#pragma unroll
                for (int n = 0; n < 4; n++) fma2(acc[m][n], a2[m], b2[n]);
        }

        k0 = kn;
        if (k0 >= kTotal) break;
        __syncthreads();
    }
}

// ----------------------------------------------------------------------------
// Kernel 1: fused Q/K/V projections  C = X @ W^T + b   (blockIdx.z selects)
// ----------------------------------------------------------------------------
__global__ void __launch_bounds__(256) proj_kernel(
    const float* __restrict__ Xq, const float* __restrict__ Xk, const float* __restrict__ Xv,
    const float* __restrict__ Wq, const float* __restrict__ Wk, const float* __restrict__ Wv,
    const float* __restrict__ bq, const float* __restrict__ bk, const float* __restrict__ bv) {
    const float *X, *W, *bias;
    float* C;
    switch (blockIdx.z) {
        case 0:  X = Xq; W = Wq; bias = bq; C = g_q; break;
        case 1:  X = Xk; W = Wk; bias = bk; C = g_k; break;
        default: X = Xv; W = Wv; bias = bv; C = g_v; break;
    }
    const int i0 = blockIdx.y * 128;
    const int j0 = blockIdx.x * 128;

    ull acc[8][4] = {};
    gemm128<true>(X, HID, W, HID, i0, j0, HID, acc);

    const int tx = threadIdx.x & 15, ty = threadIdx.x >> 4;
    float2 bb[4];
#pragma unroll
    for (int n = 0; n < 4; n++) bb[n] = *(const float2*)(bias + j0 + tx * 8 + 2 * n);
#pragma unroll
    for (int m = 0; m < 8; m++) {
        float2* crow = (float2*)(C + (size_t)(i0 + ty * 8 + m) * HID + j0 + tx * 8);
#pragma unroll
        for (int n = 0; n < 4; n++) {
            U64 u; u.u = acc[m][n];
            u.f.x += bb[n].x;
            u.f.y += bb[n].y;
            crow[n] = u.f;
        }
    }
}

// ----------------------------------------------------------------------------
// Kernel 2: scores (t-major): g_p[b][t][s] = <q_t, k_s> * SCALE, s<=t only.
// Only lower-triangular 128-tiles do work; diag tiles zero the s>t corner.
// ----------------------------------------------------------------------------
__global__ void __launch_bounds__(256) scores_kernel() {
    const int st = blockIdx.x;   // s tile
    const int tt = blockIdx.y;   // t tile
    const int b  = blockIdx.z;
    if (st > tt) return;         // strictly-masked tile: never written, never read

    const float* Aq = g_q + (size_t)b * SEQ * HID;
    const float* Bk = g_k + (size_t)b * SEQ * HID;
    float*       P  = g_p + (size_t)b * SEQ * SEQ;
    const int i0 = tt * 128;     // t rows
    const int j0 = st * 128;     // s cols

    ull acc[8][4] = {};
    gemm128<true>(Aq, HID, Bk, HID, i0, j0, HID, acc);

    const int tx = threadIdx.x & 15, ty = threadIdx.x >> 4;
#pragma unroll
    for (int m = 0; m < 8; m++) {
        const int t = i0 + ty * 8 + m;
        float2* prow = (float2*)(P + (size_t)t * SEQ + j0 + tx * 8);
#pragma unroll
        for (int n = 0; n < 4; n++) {
            const int s = j0 + tx * 8 + 2 * n;
            U64 u; u.u = acc[m][n];
            float2 o;
            o.x = (s     <= t) ? u.f.x * SCALE : 0.0f;
            o.y = (s + 1 <= t) ? u.f.y * SCALE : 0.0f;
            prow[n] = o;
        }
    }
}

// ----------------------------------------------------------------------------
// Kernel 3: in-place softmax over s for each (b, t) row of g_p (length t+1).
// ----------------------------------------------------------------------------
__global__ void __launch_bounds__(256) softmax_kernel() {
    const int t = blockIdx.x, b = blockIdx.y;
    float* row = g_p + ((size_t)b * SEQ + t) * SEQ;
    const int n = t + 1;
    const int tid = threadIdx.x;

    float v[8];
    float mx = -3.0e38f;
#pragma unroll
    for (int i = 0; i < 8; i++) {
        const int s = tid + i * 256;
        v[i] = (s < n) ? row[s] : -3.0e38f;
        mx = fmaxf(mx, v[i]);
    }

    __shared__ float red[256];
    red[tid] = mx;
    __syncthreads();
#pragma unroll
    for (int o = 128; o > 0; o >>= 1) {
        if (tid < o) red[tid] = fmaxf(red[tid], red[tid + o]);
        __syncthreads();
    }
    mx = red[0];
    __syncthreads();

    float sum = 0.0f;
#pragma unroll
    for (int i = 0; i < 8; i++) {
        const int s = tid + i * 256;
        if (s < n) { v[i] = __expf(v[i] - mx); sum += v[i]; }
    }
    red[tid] = sum;
    __syncthreads();
#pragma unroll
    for (int o = 128; o > 0; o >>= 1) {
        if (tid < o) red[tid] += red[tid + o];
        __syncthreads();
    }
    const float inv = 1.0f / red[0];
#pragma unroll
    for (int i = 0; i < 8; i++) {
        const int s = tid + i * 256;
        if (s < n) row[s] = v[i] * inv;
    }
}

// ----------------------------------------------------------------------------
// Kernel 4: attn output (B, S, T):  attn[b][s][t] = g_p[b][t][s] (0 if s>t).
// 32x32 smem transpose; fully-masked tiles write zeros without reading.
// ----------------------------------------------------------------------------
__global__ void __launch_bounds__(256) transpose_mask_kernel(float* __restrict__ attn_out) {
    const int tx = threadIdx.x, ty = threadIdx.y;
    const int t0 = blockIdx.x * 32;   // column in output / row in g_p
    const int s0 = blockIdx.y * 32;   // row in output / column in g_p
    const size_t boff = (size_t)blockIdx.z * SEQ * SEQ;
    float* Ob = attn_out + boff;

    if (s0 > t0) {  // entire tile masked (covers the never-written scratch region)
#pragma unroll
        for (int r = 0; r < 4; r++)
            Ob[(size_t)(s0 + ty + 8 * r) * SEQ + t0 + tx] = 0.0f;
        return;
    }

    const float* Pb = g_p + boff;
    __shared__ float tile[32][33];
#pragma unroll
    for (int r = 0; r < 4; r++)
        tile[ty + 8 * r][tx] = Pb[(size_t)(t0 + ty + 8 * r) * SEQ + s0 + tx];
    __syncthreads();
#pragma unroll
    for (int r = 0; r < 4; r++)
        Ob[(size_t)(s0 + ty + 8 * r) * SEQ + t0 + tx] = tile[tx][ty + 8 * r];
}

// ----------------------------------------------------------------------------
// Kernel 5: context[b][t][h] = sum_{s<=t} g_p[b][t][s] * v[b][s][h]  (NN GEMM)
// k-loop stops at the diagonal tile (masked entries inside it are exact 0).
// ----------------------------------------------------------------------------
__global__ void __launch_bounds__(256) context_kernel(float* __restrict__ out) {
    const int ht = blockIdx.x;   // h tile
    const int tt = blockIdx.y;   // t tile
    const int b  = blockIdx.z;
    const float* Ap = g_p + (size_t)b * SEQ * SEQ;
    const float* Bv = g_v + (size_t)b * SEQ * HID;
    const int i0 = tt * 128;
    const int j0 = ht * 128;

    ull acc[8][4] = {};
    gemm128<false>(Ap, SEQ, Bv, HID, i0, j0, (tt + 1) * 128, acc);

    const int tx = threadIdx.x & 15, ty = threadIdx.x >> 4;
#pragma unroll
    for (int m = 0; m < 8; m++) {
        float2* crow = (float2*)(out + (size_t)b * SEQ * HID +
                                 (size_t)(i0 + ty * 8 + m) * HID + j0 + tx * 8);
#pragma unroll
        for (int n = 0; n < 4; n++) {
            U64 u; u.u = acc[m][n];
            crow[n] = u.f;
        }
    }
}

// ----------------------------------------------------------------------------
extern "C" void kernel_launch(void* const* d_in, const int* in_sizes, int n_in,
                              void* d_out, int out_size) {
    (void)in_sizes; (void)n_in; (void)out_size;
    const float* queries = (const float*)d_in[0];
    const float* keys    = (const float*)d_in[1];
    const float* values  = (const float*)d_in[2];
    const float* Wq = (const float*)d_in[3];
    const float* bq = (const float*)d_in[4];
    const float* Wk = (const float*)d_in[5];
    const float* bk = (const float*)d_in[6];
    const float* Wv = (const float*)d_in[7];
    const float* bv = (const float*)d_in[8];

    float* ctx  = (float*)d_out;                              // (B, S, H)
    float* attn = (float*)d_out + (size_t)BATCH * SEQ * HID;  // (B, S, T)

    proj_kernel<<<dim3(HID / 128, BSROWS / 128, 3), 256>>>(
        queries, keys, values, Wq, Wk, Wv, bq, bk, bv);
    scores_kernel<<<dim3(SEQ / 128, SEQ / 128, BATCH), 256>>>();
    softmax_kernel<<<dim3(SEQ, BATCH), 256>>>();
    transpose_mask_kernel<<<dim3(SEQ / 32, SEQ / 32, BATCH), dim3(32, 8)>>>(attn);
    context_kernel<<<dim3(HID / 128, SEQ / 128, BATCH), 256>>>(ctx);
}